// round 3
// baseline (speedup 1.0000x reference)
#include <cuda_runtime.h>
#include <math.h>

#define N_NODES_MAX 16384
#define IN_DIM 512
#define MEM_DIM 256
#define VOCAB 64
#define MAX_CH 8

// Scratch (allocation-free rule: __device__ globals)
__device__ float g_X[N_NODES_MAX * MEM_DIM];   // inputs @ W_in^T + b (internal rows only)
__device__ float g_P[N_NODES_MAX * MEM_DIM];   // states @ W_ch^T (per level, absolute-indexed)
__device__ float g_D[VOCAB * MEM_DIM];         // deprel_emb @ W_dep^T

// ---------------------------------------------------------------------------
// C[m,n] = sum_k A[m*lda + k] * W[n*1024 + wofs + k]  (+ bias[n])
// 128x128 block tile, BK=16, 256 threads, 8x8 microtile, double-buffered smem.
// LEAF_TANH: rows >= first_leaf write tanh(val) to S instead of val to C.
// ---------------------------------------------------------------------------
template<bool HAS_BIAS, bool LEAF_TANH>
__global__ __launch_bounds__(256)
void gemm128(const float* __restrict__ A, int lda,
             const float* __restrict__ W, int wofs,
             const float* __restrict__ bias,
             float* __restrict__ Cmat, int M, int K,
             float* __restrict__ S, int first_leaf) {
    __shared__ float As[2][16][132];   // [buf][k][m]
    __shared__ float Bs[2][16][132];   // [buf][k][n]

    const int tid = threadIdx.x;            // 0..255
    const int bm  = blockIdx.x * 128;
    const int bn  = blockIdx.y * 128;
    const int tm  = (tid >> 4) * 8;         // 0..120
    const int tn  = (tid & 15) * 8;         // 0..120

    // loader mapping: rows r and r+64, k-quad c4
    const int lr  = tid >> 2;               // 0..63
    const int lc4 = (tid & 3) * 4;          // 0,4,8,12

    float acc[8][8] = {};

    // ---- prefetch tile 0 into registers ----
    float4 a0, a1, b0, b1;
    {
        int gm0 = bm + lr, gm1 = bm + lr + 64;
        a0 = (gm0 < M) ? *(const float4*)(A + (long)gm0 * lda + lc4)
                       : make_float4(0.f, 0.f, 0.f, 0.f);
        a1 = (gm1 < M) ? *(const float4*)(A + (long)gm1 * lda + lc4)
                       : make_float4(0.f, 0.f, 0.f, 0.f);
        b0 = *(const float4*)(W + (long)(bn + lr)      * 1024 + wofs + lc4);
        b1 = *(const float4*)(W + (long)(bn + lr + 64) * 1024 + wofs + lc4);
    }
    // store tile 0 to buffer 0 (transposed: [k][m])
    As[0][lc4+0][lr] = a0.x; As[0][lc4+1][lr] = a0.y; As[0][lc4+2][lr] = a0.z; As[0][lc4+3][lr] = a0.w;
    As[0][lc4+0][lr+64] = a1.x; As[0][lc4+1][lr+64] = a1.y; As[0][lc4+2][lr+64] = a1.z; As[0][lc4+3][lr+64] = a1.w;
    Bs[0][lc4+0][lr] = b0.x; Bs[0][lc4+1][lr] = b0.y; Bs[0][lc4+2][lr] = b0.z; Bs[0][lc4+3][lr] = b0.w;
    Bs[0][lc4+0][lr+64] = b1.x; Bs[0][lc4+1][lr+64] = b1.y; Bs[0][lc4+2][lr+64] = b1.z; Bs[0][lc4+3][lr+64] = b1.w;
    __syncthreads();

    int cur = 0;
    for (int k0 = 0; k0 < K; k0 += 16) {
        const bool has_next = (k0 + 16) < K;
        // ---- prefetch next tile to registers (overlaps with compute) ----
        if (has_next) {
            int kk = k0 + 16;
            int gm0 = bm + lr, gm1 = bm + lr + 64;
            a0 = (gm0 < M) ? *(const float4*)(A + (long)gm0 * lda + kk + lc4)
                           : make_float4(0.f, 0.f, 0.f, 0.f);
            a1 = (gm1 < M) ? *(const float4*)(A + (long)gm1 * lda + kk + lc4)
                           : make_float4(0.f, 0.f, 0.f, 0.f);
            b0 = *(const float4*)(W + (long)(bn + lr)      * 1024 + wofs + kk + lc4);
            b1 = *(const float4*)(W + (long)(bn + lr + 64) * 1024 + wofs + kk + lc4);
        }

        // ---- compute on current buffer ----
        #pragma unroll
        for (int k = 0; k < 16; ++k) {
            float4 ra0 = *(const float4*)&As[cur][k][tm];
            float4 ra1 = *(const float4*)&As[cur][k][tm + 4];
            float4 rb0 = *(const float4*)&Bs[cur][k][tn];
            float4 rb1 = *(const float4*)&Bs[cur][k][tn + 4];
            float av[8] = {ra0.x, ra0.y, ra0.z, ra0.w, ra1.x, ra1.y, ra1.z, ra1.w};
            float bv[8] = {rb0.x, rb0.y, rb0.z, rb0.w, rb1.x, rb1.y, rb1.z, rb1.w};
            #pragma unroll
            for (int u = 0; u < 8; ++u)
                #pragma unroll
                for (int v = 0; v < 8; ++v)
                    acc[u][v] += av[u] * bv[v];
        }

        // ---- store next tile to the other buffer ----
        if (has_next) {
            int nb = cur ^ 1;
            As[nb][lc4+0][lr] = a0.x; As[nb][lc4+1][lr] = a0.y; As[nb][lc4+2][lr] = a0.z; As[nb][lc4+3][lr] = a0.w;
            As[nb][lc4+0][lr+64] = a1.x; As[nb][lc4+1][lr+64] = a1.y; As[nb][lc4+2][lr+64] = a1.z; As[nb][lc4+3][lr+64] = a1.w;
            Bs[nb][lc4+0][lr] = b0.x; Bs[nb][lc4+1][lr] = b0.y; Bs[nb][lc4+2][lr] = b0.z; Bs[nb][lc4+3][lr] = b0.w;
            Bs[nb][lc4+0][lr+64] = b1.x; Bs[nb][lc4+1][lr+64] = b1.y; Bs[nb][lc4+2][lr+64] = b1.z; Bs[nb][lc4+3][lr+64] = b1.w;
            __syncthreads();
            cur = nb;
        }
    }

    // ---- epilogue ----
    float bv[8];
    #pragma unroll
    for (int v = 0; v < 8; ++v)
        bv[v] = HAS_BIAS ? bias[bn + tn + v] : 0.f;

    #pragma unroll
    for (int u = 0; u < 8; ++u) {
        int gm = bm + tm + u;
        if (gm >= M) continue;
        float vals[8];
        #pragma unroll
        for (int v = 0; v < 8; ++v) vals[v] = acc[u][v] + bv[v];

        if (LEAF_TANH && gm >= first_leaf) {
            // leaf row: states = tanh(x), X not needed
            float4 o0 = make_float4(tanhf(vals[0]), tanhf(vals[1]), tanhf(vals[2]), tanhf(vals[3]));
            float4 o1 = make_float4(tanhf(vals[4]), tanhf(vals[5]), tanhf(vals[6]), tanhf(vals[7]));
            *(float4*)(S + (long)gm * MEM_DIM + bn + tn)     = o0;
            *(float4*)(S + (long)gm * MEM_DIM + bn + tn + 4) = o1;
        } else {
            float4 o0 = make_float4(vals[0], vals[1], vals[2], vals[3]);
            float4 o1 = make_float4(vals[4], vals[5], vals[6], vals[7]);
            *(float4*)(Cmat + (long)gm * MEM_DIM + bn + tn)     = o0;
            *(float4*)(Cmat + (long)gm * MEM_DIM + bn + tn + 4) = o1;
        }
    }
}

// ---------------------------------------------------------------------------
// Combine: one block per node, 256 threads (one per feature).
// r[k,f] = tanh(X[i,f] + D[cdep,f] + P[child,f]) for real children (prefix of
// length C); pooled out[f] = max_{t<C} flat[f*C + t] over row-major r[:C].
// The reference's min(j//M, K-1) clamp is dead: f*C+t <= 256*C-1 stays inside
// the first C rows, so only real children are ever read.
// ---------------------------------------------------------------------------
__global__ void combine_k(int lo,
                          const int*   __restrict__ cidx,
                          const int*   __restrict__ cdep,
                          const int*   __restrict__ counts,
                          const float* __restrict__ X,
                          const float* __restrict__ D,
                          const float* __restrict__ P,
                          float*       __restrict__ S) {
    const int i = lo + (int)blockIdx.x;
    const int f = threadIdx.x;
    __shared__ float r[MAX_CH * MEM_DIM];

    const int cnt = counts[i];
    const float x = X[(long)i * MEM_DIM + f];

    if (cnt == 0) {               // leaf-style fallback (not expected in this range)
        S[(long)i * MEM_DIM + f] = tanhf(x);
        return;
    }
    const int C = cnt;

    #pragma unroll
    for (int k = 0; k < MAX_CH; ++k) {
        int c = cidx[i * MAX_CH + k];
        if (c >= 0) {
            int dv = cdep[i * MAX_CH + k];
            r[k * MEM_DIM + f] =
                tanhf(x + D[dv * MEM_DIM + f] + P[(long)c * MEM_DIM + f]);
        }
    }
    __syncthreads();

    float m = -3.402823466e38f;
    for (int t = 0; t < C; ++t)
        m = fmaxf(m, r[f * C + t]);

    S[(long)i * MEM_DIM + f] = m;
}

// ---------------------------------------------------------------------------
extern "C" void kernel_launch(void* const* d_in, const int* in_sizes, int n_in,
                              void* d_out, int out_size) {
    const float* inputs    = (const float*)d_in[0];   // [N, 512]
    const float* W         = (const float*)d_in[1];   // [256, 1024]
    const float* bvec      = (const float*)d_in[2];   // [256]
    const float* deprel    = (const float*)d_in[3];   // [64, 256]
    const int*   child_idx = (const int*)  d_in[4];   // [N, 8]
    const int*   child_dep = (const int*)  d_in[5];   // [N, 8]
    const int*   counts    = (const int*)  d_in[6];   // [N]
    float*       states    = (float*)d_out;           // [N, 256]

    float *X = nullptr, *P = nullptr, *D = nullptr;
    cudaGetSymbolAddress((void**)&X, g_X);
    cudaGetSymbolAddress((void**)&P, g_P);
    cudaGetSymbolAddress((void**)&D, g_D);

    const int N = in_sizes[0] / IN_DIM;               // 16384
    const int first_leaf = (N + MAX_CH - 2) / MAX_CH; // ceil((N-1)/8) = 2048

    // Phase 0: input projection + bias; leaf rows get tanh fused into epilogue.
    gemm128<true, true><<<dim3((unsigned)((N + 127) / 128), 2), 256>>>(
        inputs, IN_DIM, W, 0, bvec, X, N, IN_DIM, states, first_leaf);
    // deprel projection (tiny)
    gemm128<false, false><<<dim3(1, 2), 256>>>(
        deprel, MEM_DIM, W, IN_DIM, nullptr, D, VOCAB, MEM_DIM, nullptr, 0);

    // Level starts: s[L] = (8^L - 1)/7
    long s[12];
    s[0] = 0;
    int nl = 0;
    while (s[nl] < N) { s[nl + 1] = 8 * s[nl] + 1; nl++; }

    // Internal levels, bottom-up
    for (int L = nl - 1; L >= 0; --L) {
        long lo = s[L];
        long hi = s[L + 1] - 1;
        if (hi > first_leaf - 1) hi = first_leaf - 1;
        if (lo > hi) continue;

        long clo = 8 * lo + 1;
        long chi = 8 * hi + 8;
        if (chi > N - 1) chi = N - 1;
        int Mc = (int)(chi - clo + 1);

        // P[j] = states[j] @ W_ch^T for all children of this level (contiguous range)
        gemm128<false, false><<<dim3((unsigned)((Mc + 127) / 128), 2), 256>>>(
            states + clo * MEM_DIM, MEM_DIM, W, IN_DIM + MEM_DIM, nullptr,
            P + clo * MEM_DIM, Mc, MEM_DIM, nullptr, 0);

        combine_k<<<(unsigned)(hi - lo + 1), 256>>>(
            (int)lo, child_idx, child_dep, counts, X, D, P, states);
    }
}

// round 6
// speedup vs baseline: 1.2136x; 1.2136x over previous
#include <cuda_runtime.h>
#include <math.h>

#define N_NODES_MAX 16384
#define IN_DIM 512
#define MEM_DIM 256
#define VOCAB 64
#define MAX_CH 8

// Scratch (allocation-free rule: __device__ globals)
__device__ float g_X[N_NODES_MAX * MEM_DIM];   // inputs @ W_in^T + b (internal rows)
__device__ float g_P[N_NODES_MAX * MEM_DIM];   // states @ W_ch^T (per level, absolute-indexed)
__device__ float g_D[VOCAB * MEM_DIM];         // deprel_emb @ W_dep^T

// ---------------------------------------------------------------------------
// C[m,n] = sum_k A[m*lda + k] * W[n*1024 + wofs + k]  (+ bias[n])
// 128(M) x 64(N) block tile, BK=16, 256 threads, 8x4 microtile, double-buffered.
// LEAF_TANH: rows >= first_leaf write tanh(val) to S instead of val to C.
// ---------------------------------------------------------------------------
template<bool HAS_BIAS, bool LEAF_TANH>
__global__ __launch_bounds__(256)
void rcnn_gemm(const float* __restrict__ A, int lda,
               const float* __restrict__ W, int wofs,
               const float* __restrict__ bias,
               float* __restrict__ Cmat, int M, int K,
               float* __restrict__ S, int first_leaf) {
    __shared__ float As[2][16][132];   // [buf][k][m] (128 + pad)
    __shared__ float Bs[2][16][68];    // [buf][k][n] (64 + pad)

    const int tid = threadIdx.x;            // 0..255
    const int bm  = blockIdx.x * 128;
    const int bn  = blockIdx.y * 64;
    const int tm  = (tid >> 4) * 8;         // 0..120
    const int tn  = (tid & 15) * 4;         // 0..60

    // loader mapping
    const int lr  = tid >> 2;               // 0..63
    const int lc4 = (tid & 3) * 4;          // 0,4,8,12

    float c00=0.f,c01=0.f,c02=0.f,c03=0.f, c10=0.f,c11=0.f,c12=0.f,c13=0.f;
    float c20=0.f,c21=0.f,c22=0.f,c23=0.f, c30=0.f,c31=0.f,c32=0.f,c33=0.f;
    float c40=0.f,c41=0.f,c42=0.f,c43=0.f, c50=0.f,c51=0.f,c52=0.f,c53=0.f;
    float c60=0.f,c61=0.f,c62=0.f,c63=0.f, c70=0.f,c71=0.f,c72=0.f,c73=0.f;

    float4 a0, a1, b0;
    // ---- prefetch tile 0 ----
    {
        int gm0 = bm + lr, gm1 = bm + lr + 64;
        a0 = (gm0 < M) ? *(const float4*)(A + (long)gm0 * lda + lc4)
                       : make_float4(0.f, 0.f, 0.f, 0.f);
        a1 = (gm1 < M) ? *(const float4*)(A + (long)gm1 * lda + lc4)
                       : make_float4(0.f, 0.f, 0.f, 0.f);
        b0 = *(const float4*)(W + (long)(bn + lr) * 1024 + wofs + lc4);
    }
    As[0][lc4+0][lr] = a0.x; As[0][lc4+1][lr] = a0.y; As[0][lc4+2][lr] = a0.z; As[0][lc4+3][lr] = a0.w;
    As[0][lc4+0][lr+64] = a1.x; As[0][lc4+1][lr+64] = a1.y; As[0][lc4+2][lr+64] = a1.z; As[0][lc4+3][lr+64] = a1.w;
    Bs[0][lc4+0][lr] = b0.x; Bs[0][lc4+1][lr] = b0.y; Bs[0][lc4+2][lr] = b0.z; Bs[0][lc4+3][lr] = b0.w;
    __syncthreads();

    int cur = 0;
    for (int k0 = 0; k0 < K; k0 += 16) {
        const bool has_next = (k0 + 16) < K;
        if (has_next) {
            int kk = k0 + 16;
            int gm0 = bm + lr, gm1 = bm + lr + 64;
            a0 = (gm0 < M) ? *(const float4*)(A + (long)gm0 * lda + kk + lc4)
                           : make_float4(0.f, 0.f, 0.f, 0.f);
            a1 = (gm1 < M) ? *(const float4*)(A + (long)gm1 * lda + kk + lc4)
                           : make_float4(0.f, 0.f, 0.f, 0.f);
            b0 = *(const float4*)(W + (long)(bn + lr) * 1024 + wofs + kk + lc4);
        }

        #pragma unroll
        for (int k = 0; k < 16; ++k) {
            const float4 ra0 = *(const float4*)&As[cur][k][tm];
            const float4 ra1 = *(const float4*)&As[cur][k][tm + 4];
            const float4 rb  = *(const float4*)&Bs[cur][k][tn];
            c00 += ra0.x*rb.x; c01 += ra0.x*rb.y; c02 += ra0.x*rb.z; c03 += ra0.x*rb.w;
            c10 += ra0.y*rb.x; c11 += ra0.y*rb.y; c12 += ra0.y*rb.z; c13 += ra0.y*rb.w;
            c20 += ra0.z*rb.x; c21 += ra0.z*rb.y; c22 += ra0.z*rb.z; c23 += ra0.z*rb.w;
            c30 += ra0.w*rb.x; c31 += ra0.w*rb.y; c32 += ra0.w*rb.z; c33 += ra0.w*rb.w;
            c40 += ra1.x*rb.x; c41 += ra1.x*rb.y; c42 += ra1.x*rb.z; c43 += ra1.x*rb.w;
            c50 += ra1.y*rb.x; c51 += ra1.y*rb.y; c52 += ra1.y*rb.z; c53 += ra1.y*rb.w;
            c60 += ra1.z*rb.x; c61 += ra1.z*rb.y; c62 += ra1.z*rb.z; c63 += ra1.z*rb.w;
            c70 += ra1.w*rb.x; c71 += ra1.w*rb.y; c72 += ra1.w*rb.z; c73 += ra1.w*rb.w;
        }

        if (has_next) {
            int nb = cur ^ 1;
            As[nb][lc4+0][lr] = a0.x; As[nb][lc4+1][lr] = a0.y; As[nb][lc4+2][lr] = a0.z; As[nb][lc4+3][lr] = a0.w;
            As[nb][lc4+0][lr+64] = a1.x; As[nb][lc4+1][lr+64] = a1.y; As[nb][lc4+2][lr+64] = a1.z; As[nb][lc4+3][lr+64] = a1.w;
            Bs[nb][lc4+0][lr] = b0.x; Bs[nb][lc4+1][lr] = b0.y; Bs[nb][lc4+2][lr] = b0.z; Bs[nb][lc4+3][lr] = b0.w;
            __syncthreads();
            cur = nb;
        }
    }

    // ---- epilogue ----
    const float bb0 = HAS_BIAS ? bias[bn + tn + 0] : 0.f;
    const float bb1 = HAS_BIAS ? bias[bn + tn + 1] : 0.f;
    const float bb2 = HAS_BIAS ? bias[bn + tn + 2] : 0.f;
    const float bb3 = HAS_BIAS ? bias[bn + tn + 3] : 0.f;

    float rowv[8][4] = {
        {c00,c01,c02,c03},{c10,c11,c12,c13},{c20,c21,c22,c23},{c30,c31,c32,c33},
        {c40,c41,c42,c43},{c50,c51,c52,c53},{c60,c61,c62,c63},{c70,c71,c72,c73}};

    #pragma unroll
    for (int u = 0; u < 8; ++u) {
        int gm = bm + tm + u;
        if (gm >= M) continue;
        float v0 = rowv[u][0] + bb0;
        float v1 = rowv[u][1] + bb1;
        float v2 = rowv[u][2] + bb2;
        float v3 = rowv[u][3] + bb3;
        if (LEAF_TANH && gm >= first_leaf) {
            *(float4*)(S + (long)gm * MEM_DIM + bn + tn) =
                make_float4(tanhf(v0), tanhf(v1), tanhf(v2), tanhf(v3));
        } else {
            *(float4*)(Cmat + (long)gm * MEM_DIM + bn + tn) =
                make_float4(v0, v1, v2, v3);
        }
    }
}

// ---------------------------------------------------------------------------
// Combine, warp-per-child fast path (C == 8, the common case).
// Reference maxpool: out[f] = max_{t<C} flat[f*C+t], flat = row-major r[C][256].
// For C=8: j = 8f+t -> child row = j>>8 = f>>5 (= warp id), feature = 8*(f&31)+t.
// So warp w lane l computes r for child w at features 8l..8l+7, maxes locally.
// Generic path (C != 8): smem materialization of r[:C], then flat maxpool.
// ---------------------------------------------------------------------------
__global__ __launch_bounds__(256)
void rcnn_combine(int lo,
                  const int*   __restrict__ cidx,
                  const int*   __restrict__ cdep,
                  const int*   __restrict__ counts,
                  const float* __restrict__ X,
                  const float* __restrict__ D,
                  const float* __restrict__ P,
                  float*       __restrict__ S) {
    const int i   = lo + (int)blockIdx.x;
    const int tid = threadIdx.x;
    const int cnt = counts[i];

    __shared__ float r[MAX_CH * MEM_DIM];

    if (cnt == 8) {
        const int w = tid >> 5;            // warp id = child slot
        const int l = tid & 31;            // lane
        const int g = l * 8;               // feature base 8l

        const int c  = cidx[i * MAX_CH + w];
        const int dv = cdep[i * MAX_CH + w];

        const float4 x0 = *(const float4*)(X + (long)i  * MEM_DIM + g);
        const float4 x1 = *(const float4*)(X + (long)i  * MEM_DIM + g + 4);
        const float4 d0 = *(const float4*)(D + (long)dv * MEM_DIM + g);
        const float4 d1 = *(const float4*)(D + (long)dv * MEM_DIM + g + 4);
        const float4 p0 = *(const float4*)(P + (long)c  * MEM_DIM + g);
        const float4 p1 = *(const float4*)(P + (long)c  * MEM_DIM + g + 4);

        float m = tanhf(x0.x + d0.x + p0.x);
        m = fmaxf(m, tanhf(x0.y + d0.y + p0.y));
        m = fmaxf(m, tanhf(x0.z + d0.z + p0.z));
        m = fmaxf(m, tanhf(x0.w + d0.w + p0.w));
        m = fmaxf(m, tanhf(x1.x + d1.x + p1.x));
        m = fmaxf(m, tanhf(x1.y + d1.y + p1.y));
        m = fmaxf(m, tanhf(x1.z + d1.z + p1.z));
        m = fmaxf(m, tanhf(x1.w + d1.w + p1.w));

        S[(long)i * MEM_DIM + w * 32 + l] = m;
        return;
    }

    // ---- generic path (rare: C != 8) ----
    const int f = tid;
    const float x = X[(long)i * MEM_DIM + f];

    if (cnt == 0) {
        S[(long)i * MEM_DIM + f] = tanhf(x);
        return;
    }
    const int C = cnt;

    for (int k = 0; k < C; ++k) {
        int c  = cidx[i * MAX_CH + k];
        int dv = cdep[i * MAX_CH + k];
        r[k * MEM_DIM + f] = tanhf(x + D[dv * MEM_DIM + f] + P[(long)c * MEM_DIM + f]);
    }
    __syncthreads();

    float m = -3.402823466e38f;
    for (int t = 0; t < C; ++t) {
        int j = f * C + t;
        m = fmaxf(m, r[(j >> 8) * MEM_DIM + (j & 255)]);
    }
    S[(long)i * MEM_DIM + f] = m;
}

// ---------------------------------------------------------------------------
extern "C" void kernel_launch(void* const* d_in, const int* in_sizes, int n_in,
                              void* d_out, int out_size) {
    const float* inputs    = (const float*)d_in[0];   // [N, 512]
    const float* W         = (const float*)d_in[1];   // [256, 1024]
    const float* bvec      = (const float*)d_in[2];   // [256]
    const float* deprel    = (const float*)d_in[3];   // [64, 256]
    const int*   child_idx = (const int*)  d_in[4];   // [N, 8]
    const int*   child_dep = (const int*)  d_in[5];   // [N, 8]
    const int*   counts    = (const int*)  d_in[6];   // [N]
    float*       states    = (float*)d_out;           // [N, 256]

    float *X = nullptr, *P = nullptr, *D = nullptr;
    cudaGetSymbolAddress((void**)&X, g_X);
    cudaGetSymbolAddress((void**)&P, g_P);
    cudaGetSymbolAddress((void**)&D, g_D);

    const int N = in_sizes[0] / IN_DIM;               // 16384
    const int first_leaf = (N + MAX_CH - 2) / MAX_CH; // ceil((N-1)/8) = 2048

    // Phase 0: input projection + bias; leaf rows get tanh fused into epilogue.
    rcnn_gemm<true, true><<<dim3((unsigned)((N + 127) / 128), 4), 256>>>(
        inputs, IN_DIM, W, 0, bvec, X, N, IN_DIM, states, first_leaf);
    // deprel projection (tiny)
    rcnn_gemm<false, false><<<dim3(1, 4), 256>>>(
        deprel, MEM_DIM, W, IN_DIM, nullptr, D, VOCAB, MEM_DIM, nullptr, 0);

    // Level starts: s[L] = (8^L - 1)/7
    long s[12];
    s[0] = 0;
    int nl = 0;
    while (s[nl] < N) { s[nl + 1] = 8 * s[nl] + 1; nl++; }

    // Internal levels, bottom-up
    for (int L = nl - 1; L >= 0; --L) {
        long lo = s[L];
        long hi = s[L + 1] - 1;
        if (hi > first_leaf - 1) hi = first_leaf - 1;
        if (lo > hi) continue;

        long clo = 8 * lo + 1;
        long chi = 8 * hi + 8;
        if (chi > N - 1) chi = N - 1;
        int Mc = (int)(chi - clo + 1);

        // P[j] = states[j] @ W_ch^T for all children of this level (contiguous)
        rcnn_gemm<false, false><<<dim3((unsigned)((Mc + 127) / 128), 4), 256>>>(
            states + clo * MEM_DIM, MEM_DIM, W, IN_DIM + MEM_DIM, nullptr,
            P + clo * MEM_DIM, Mc, MEM_DIM, nullptr, 0);

        rcnn_combine<<<(unsigned)(hi - lo + 1), 256>>>(
            (int)lo, child_idx, child_dep, counts, X, D, P, states);
    }
}

// round 9
// speedup vs baseline: 1.8884x; 1.5560x over previous
#include <cuda_runtime.h>
#include <cuda_bf16.h>
#include <stdint.h>
#include <math.h>

#define N_NODES_MAX 16384
#define IN_DIM 512
#define MEM_DIM 256
#define VOCAB 64
#define MAX_CH 8

// Scratch (allocation-free rule: __device__ globals)
__device__ float g_X[N_NODES_MAX * MEM_DIM];   // inputs @ W_in^T + b (internal rows)
__device__ float g_P[N_NODES_MAX * MEM_DIM];   // states @ W_ch^T (per level)
__device__ float g_D[VOCAB * MEM_DIM];         // deprel_emb @ W_dep^T

#define AROW 24   // bf16 elements per smem row: 16 data + 8 pad (48B, 16B-aligned)
#define BROW 24

__device__ __forceinline__ void ldsm4(unsigned& r0, unsigned& r1,
                                      unsigned& r2, unsigned& r3, unsigned addr) {
    asm volatile("ldmatrix.sync.aligned.m8n8.x4.shared.b16 {%0,%1,%2,%3}, [%4];"
                 : "=r"(r0), "=r"(r1), "=r"(r2), "=r"(r3) : "r"(addr));
}

__device__ __forceinline__ void mma16816(float* c,
                                         unsigned a0, unsigned a1, unsigned a2, unsigned a3,
                                         unsigned b0, unsigned b1) {
    asm volatile(
        "mma.sync.aligned.m16n8k16.row.col.f32.bf16.bf16.f32 "
        "{%0,%1,%2,%3}, {%4,%5,%6,%7}, {%8,%9}, {%0,%1,%2,%3};"
        : "+f"(c[0]), "+f"(c[1]), "+f"(c[2]), "+f"(c[3])
        : "r"(a0), "r"(a1), "r"(a2), "r"(a3), "r"(b0), "r"(b1));
}

// split two fp32 into bf16 hi pair + bf16 lo pair (x = hi + lo to ~bf16^2 precision)
__device__ __forceinline__ void split2(float x, float y,
                                       __nv_bfloat162& hi, __nv_bfloat162& lo) {
    __nv_bfloat16 hx = __float2bfloat16(x);
    __nv_bfloat16 hy = __float2bfloat16(y);
    hi = __halves2bfloat162(hx, hy);
    lo = __halves2bfloat162(__float2bfloat16(x - __bfloat162float(hx)),
                            __float2bfloat16(y - __bfloat162float(hy)));
}

__device__ __forceinline__ void store_a8(__nv_bfloat16* hb, __nv_bfloat16* lb,
                                         int row, int k, float4 v0, float4 v1) {
    __nv_bfloat162 h, l;
    __nv_bfloat162* hp = (__nv_bfloat162*)(hb + row * AROW + k);
    __nv_bfloat162* lp = (__nv_bfloat162*)(lb + row * AROW + k);
    split2(v0.x, v0.y, h, l); hp[0] = h; lp[0] = l;
    split2(v0.z, v0.w, h, l); hp[1] = h; lp[1] = l;
    split2(v1.x, v1.y, h, l); hp[2] = h; lp[2] = l;
    split2(v1.z, v1.w, h, l); hp[3] = h; lp[3] = l;
}

__device__ __forceinline__ void store_b4(__nv_bfloat16* hb, __nv_bfloat16* lb,
                                         int row, int k, float4 v) {
    __nv_bfloat162 h, l;
    __nv_bfloat162* hp = (__nv_bfloat162*)(hb + row * BROW + k);
    __nv_bfloat162* lp = (__nv_bfloat162*)(lb + row * BROW + k);
    split2(v.x, v.y, h, l); hp[0] = h; lp[0] = l;
    split2(v.z, v.w, h, l); hp[1] = h; lp[1] = l;
}

// ---------------------------------------------------------------------------
// C[m,n] = sum_k A[m*lda+k] * W[n*1024 + wofs + k]  (+ bias[n])
// Split-bf16 3-pass tensor-core GEMM: C ~= Ah*Wh + Ah*Wl + Al*Wh, fp32 accum.
// Block 128(M) x 64(N), BK=16 double-buffered, 8 warps (4x2), warp tile 32x32.
// LEAF_TANH: rows >= first_leaf write tanh(val) to S instead of val to C.
// ---------------------------------------------------------------------------
template<bool HAS_BIAS, bool LEAF_TANH>
__global__ __launch_bounds__(256)
void rcnn_gemm_mma(const float* __restrict__ A, int lda,
                   const float* __restrict__ W, int wofs,
                   const float* __restrict__ bias,
                   float* __restrict__ Cmat, int M, int K,
                   float* __restrict__ S, int first_leaf) {
    __shared__ __nv_bfloat16 sAh[2][128 * AROW];
    __shared__ __nv_bfloat16 sAl[2][128 * AROW];
    __shared__ __nv_bfloat16 sBh[2][64 * BROW];
    __shared__ __nv_bfloat16 sBl[2][64 * BROW];

    const int tid  = threadIdx.x;
    const int lane = tid & 31;
    const int warp = tid >> 5;
    const int wm   = warp >> 1;          // 0..3  (M direction, 32 rows each)
    const int wn   = warp & 1;           // 0..1  (N direction, 32 cols each)
    const int bm   = blockIdx.x * 128;
    const int bn   = blockIdx.y * 64;

    // gmem loader mapping
    const int arow = tid >> 1;           // 0..127
    const int ak   = (tid & 1) * 8;      // 0 or 8
    const int brow = tid >> 2;           // 0..63
    const int bk   = (tid & 3) * 4;      // 0,4,8,12

    float acc[2][4][4];
    #pragma unroll
    for (int i = 0; i < 2; ++i) {
        #pragma unroll
        for (int j = 0; j < 4; ++j) {
            #pragma unroll
            for (int q = 0; q < 4; ++q) { acc[i][j][q] = 0.f; }
        }
    }

    const float4 z4 = make_float4(0.f, 0.f, 0.f, 0.f);
    const int gm = bm + arow;
    const bool arow_ok = (gm < M);

    // prefetch + store k-tile 0
    float4 a0 = arow_ok ? *(const float4*)(A + (long)gm * lda + ak)     : z4;
    float4 a1 = arow_ok ? *(const float4*)(A + (long)gm * lda + ak + 4) : z4;
    float4 bv = *(const float4*)(W + (long)(bn + brow) * 1024 + wofs + bk);
    store_a8(sAh[0], sAl[0], arow, ak, a0, a1);
    store_b4(sBh[0], sBl[0], brow, bk, bv);
    __syncthreads();

    // ldmatrix per-thread source coordinates (constant per thread)
    const int gq8 = lane >> 3;           // 0..3 matrix group
    const int wi  = lane & 7;
    const int a_row = wm * 32 + wi + 8 * (gq8 & 1);     // plus mt*16 below
    const int a_kh  = (gq8 >> 1) * 8;
    const int b_row = wn * 32 + wi + 8 * (gq8 >> 1);    // plus p*16 below
    const int b_kh  = (gq8 & 1) * 8;

    int cur = 0;
    for (int k0 = 0; k0 < K; k0 += 16) {
        const bool has_next = (k0 + 16) < K;
        if (has_next) {
            a0 = arow_ok ? *(const float4*)(A + (long)gm * lda + k0 + 16 + ak)     : z4;
            a1 = arow_ok ? *(const float4*)(A + (long)gm * lda + k0 + 16 + ak + 4) : z4;
            bv = *(const float4*)(W + (long)(bn + brow) * 1024 + wofs + k0 + 16 + bk);
        }

        // load fragments
        unsigned Ah[2][4], Al[2][4], Bh[2][4], Bl[2][4];
        #pragma unroll
        for (int mt = 0; mt < 2; ++mt) {
            unsigned off = (unsigned)((a_row + mt * 16) * AROW + a_kh) * 2u;
            unsigned ah = (unsigned)__cvta_generic_to_shared(sAh[cur]) + off;
            unsigned al = (unsigned)__cvta_generic_to_shared(sAl[cur]) + off;
            ldsm4(Ah[mt][0], Ah[mt][1], Ah[mt][2], Ah[mt][3], ah);
            ldsm4(Al[mt][0], Al[mt][1], Al[mt][2], Al[mt][3], al);
        }
        #pragma unroll
        for (int p = 0; p < 2; ++p) {
            unsigned off = (unsigned)((b_row + p * 16) * BROW + b_kh) * 2u;
            unsigned bh = (unsigned)__cvta_generic_to_shared(sBh[cur]) + off;
            unsigned bl = (unsigned)__cvta_generic_to_shared(sBl[cur]) + off;
            ldsm4(Bh[p][0], Bh[p][1], Bh[p][2], Bh[p][3], bh);
            ldsm4(Bl[p][0], Bl[p][1], Bl[p][2], Bl[p][3], bl);
        }

        // 3-pass MMA: hi*hi + hi*lo + lo*hi
        #pragma unroll
        for (int mt = 0; mt < 2; ++mt) {
            #pragma unroll
            for (int p = 0; p < 2; ++p) {
                #pragma unroll
                for (int nh = 0; nh < 2; ++nh) {
                    float* c = acc[mt][2 * p + nh];
                    mma16816(c, Ah[mt][0], Ah[mt][1], Ah[mt][2], Ah[mt][3],
                             Bh[p][2 * nh], Bh[p][2 * nh + 1]);
                    mma16816(c, Ah[mt][0], Ah[mt][1], Ah[mt][2], Ah[mt][3],
                             Bl[p][2 * nh], Bl[p][2 * nh + 1]);
                    mma16816(c, Al[mt][0], Al[mt][1], Al[mt][2], Al[mt][3],
                             Bh[p][2 * nh], Bh[p][2 * nh + 1]);
                }
            }
        }

        if (has_next) {
            const int nb = cur ^ 1;
            store_a8(sAh[nb], sAl[nb], arow, ak, a0, a1);
            store_b4(sBh[nb], sBl[nb], brow, bk, bv);
            __syncthreads();
            cur = nb;
        }
    }

    // epilogue: acc[mt][nt] = {c0,c1 (row gq), c2,c3 (row gq+8)}, cols 2*tig
    const int gq  = lane >> 2;
    const int tig = lane & 3;
    #pragma unroll
    for (int mt = 0; mt < 2; ++mt) {
        #pragma unroll
        for (int rh = 0; rh < 2; ++rh) {
            const int row = bm + wm * 32 + mt * 16 + rh * 8 + gq;
            if (row >= M) continue;
            const bool leaf = LEAF_TANH && (row >= first_leaf);
            float* out = leaf ? S : Cmat;
            #pragma unroll
            for (int nt = 0; nt < 4; ++nt) {
                const int col = bn + wn * 32 + nt * 8 + 2 * tig;
                float v0 = acc[mt][nt][2 * rh + 0];
                float v1 = acc[mt][nt][2 * rh + 1];
                if (HAS_BIAS) { v0 += bias[col]; v1 += bias[col + 1]; }
                if (leaf) { v0 = tanhf(v0); v1 = tanhf(v1); }
                *(float2*)(out + (long)row * MEM_DIM + col) = make_float2(v0, v1);
            }
        }
    }
}

// ---------------------------------------------------------------------------
// Combine, warp-per-child fast path (C == 8, the common case).
// Reference maxpool: out[f] = max over t<C of flat[f*C+t], flat = row-major
// r[C][256]. For C=8: j = 8f+t -> child row = f>>5 (= warp id), feature =
// 8*(f&31)+t. Warp w lane l computes child w features 8l..8l+7, maxes locally.
// Generic path (C != 8): smem materialization of r[:C], then flat maxpool.
// ---------------------------------------------------------------------------
__global__ __launch_bounds__(256)
void rcnn_combine(int lo,
                  const int*   __restrict__ cidx,
                  const int*   __restrict__ cdep,
                  const int*   __restrict__ counts,
                  const float* __restrict__ X,
                  const float* __restrict__ D,
                  const float* __restrict__ P,
                  float*       __restrict__ S) {
    const int i   = lo + (int)blockIdx.x;
    const int tid = threadIdx.x;
    const int cnt = counts[i];

    __shared__ float r[MAX_CH * MEM_DIM];

    if (cnt == 8) {
        const int w = tid >> 5;
        const int l = tid & 31;
        const int g = l * 8;

        const int c  = cidx[i * MAX_CH + w];
        const int dv = cdep[i * MAX_CH + w];

        const float4 x0 = *(const float4*)(X + (long)i  * MEM_DIM + g);
        const float4 x1 = *(const float4*)(X + (long)i  * MEM_DIM + g + 4);
        const float4 d0 = *(const float4*)(D + (long)dv * MEM_DIM + g);
        const float4 d1 = *(const float4*)(D + (long)dv * MEM_DIM + g + 4);
        const float4 p0 = *(const float4*)(P + (long)c  * MEM_DIM + g);
        const float4 p1 = *(const float4*)(P + (long)c  * MEM_DIM + g + 4);

        float m = tanhf(x0.x + d0.x + p0.x);
        m = fmaxf(m, tanhf(x0.y + d0.y + p0.y));
        m = fmaxf(m, tanhf(x0.z + d0.z + p0.z));
        m = fmaxf(m, tanhf(x0.w + d0.w + p0.w));
        m = fmaxf(m, tanhf(x1.x + d1.x + p1.x));
        m = fmaxf(m, tanhf(x1.y + d1.y + p1.y));
        m = fmaxf(m, tanhf(x1.z + d1.z + p1.z));
        m = fmaxf(m, tanhf(x1.w + d1.w + p1.w));

        S[(long)i * MEM_DIM + w * 32 + l] = m;
        return;
    }

    // generic path (rare: C != 8)
    const int f = tid;
    const float x = X[(long)i * MEM_DIM + f];

    if (cnt == 0) {
        S[(long)i * MEM_DIM + f] = tanhf(x);
        return;
    }
    const int C = cnt;

    for (int k = 0; k < C; ++k) {
        int c  = cidx[i * MAX_CH + k];
        int dv = cdep[i * MAX_CH + k];
        r[k * MEM_DIM + f] = tanhf(x + D[dv * MEM_DIM + f] + P[(long)c * MEM_DIM + f]);
    }
    __syncthreads();

    float mx = -3.402823466e38f;
    for (int t = 0; t < C; ++t) {
        int j = f * C + t;
        mx = fmaxf(mx, r[(j >> 8) * MEM_DIM + (j & 255)]);
    }
    S[(long)i * MEM_DIM + f] = mx;
}

// ---------------------------------------------------------------------------
extern "C" void kernel_launch(void* const* d_in, const int* in_sizes, int n_in,
                              void* d_out, int out_size) {
    const float* inputs    = (const float*)d_in[0];   // [N, 512]
    const float* W         = (const float*)d_in[1];   // [256, 1024]
    const float* bvec      = (const float*)d_in[2];   // [256]
    const float* deprel    = (const float*)d_in[3];   // [64, 256]
    const int*   child_idx = (const int*)  d_in[4];   // [N, 8]
    const int*   child_dep = (const int*)  d_in[5];   // [N, 8]
    const int*   counts    = (const int*)  d_in[6];   // [N]
    float*       states    = (float*)d_out;           // [N, 256]

    float *X = nullptr, *P = nullptr, *D = nullptr;
    cudaGetSymbolAddress((void**)&X, g_X);
    cudaGetSymbolAddress((void**)&P, g_P);
    cudaGetSymbolAddress((void**)&D, g_D);

    const int N = in_sizes[0] / IN_DIM;               // 16384
    const int first_leaf = (N + MAX_CH - 2) / MAX_CH; // ceil((N-1)/8) = 2048

    // Phase 0: input projection + bias; leaf rows get tanh fused into epilogue.
    rcnn_gemm_mma<true, true><<<dim3((unsigned)((N + 127) / 128), 4), 256>>>(
        inputs, IN_DIM, W, 0, bvec, X, N, IN_DIM, states, first_leaf);
    // deprel projection (tiny)
    rcnn_gemm_mma<false, false><<<dim3(1, 4), 256>>>(
        deprel, MEM_DIM, W, IN_DIM, nullptr, D, VOCAB, MEM_DIM, nullptr, 0);

    // Level starts: s[L] = (8^L - 1)/7
    long s[12];
    s[0] = 0;
    int nl = 0;
    while (s[nl] < N) { s[nl + 1] = 8 * s[nl] + 1; nl++; }

    // Internal levels, bottom-up
    for (int L = nl - 1; L >= 0; --L) {
        long lo = s[L];
        long hi = s[L + 1] - 1;
        if (hi > first_leaf - 1) hi = first_leaf - 1;
        if (lo > hi) continue;

        long clo = 8 * lo + 1;
        long chi = 8 * hi + 8;
        if (chi > N - 1) chi = N - 1;
        int Mc = (int)(chi - clo + 1);

        // P[j] = states[j] @ W_ch^T for all children of this level (contiguous)
        rcnn_gemm_mma<false, false><<<dim3((unsigned)((Mc + 127) / 128), 4), 256>>>(
            states + clo * MEM_DIM, MEM_DIM, W, IN_DIM + MEM_DIM, nullptr,
            P + clo * MEM_DIM, Mc, MEM_DIM, nullptr, 0);

        rcnn_combine<<<(unsigned)(hi - lo + 1), 256>>>(
            (int)lo, child_idx, child_dep, counts, X, D, P, states);
    }
}